// round 7
// baseline (speedup 1.0000x reference)
#include <cuda_runtime.h>
#include <cuda_fp16.h>

#define NN 100000
#define EE 3200000

// ---------------- persistent device scratch ----------------
__device__ int    g_deg[NN];
__device__ int    g_cursor[NN];      // absolute fill cursor
__device__ int    g_rowstart[NN + 1];
__device__ int    g_bsum[512];
__device__ int    g_csr[EE];
__device__ float  g_dis[NN];
__device__ uint2  g_hA16[NN * 4];    // h~ fp16: 16 halves = 32 B/node (4x uint2)
__device__ uint2  g_hB16[NN * 4];
__device__ float4 g_aggA[NN * 4];    // aggregates stay fp32 (linear access)
__device__ float4 g_aggB[NN * 4];
__device__ float2 g_h3[NN];          // layer-3 h~ (2 f32/node)

// ---------------- fp16 pack/unpack ----------------
__device__ __forceinline__ unsigned pack2(float a, float b) {
    __half2 h = __floats2half2_rn(a, b);
    return *reinterpret_cast<unsigned*>(&h);
}
__device__ __forceinline__ float2 unpack2(unsigned u) {
    __half2 h = *reinterpret_cast<__half2*>(&u);
    return __half22float2(h);
}

// ---------------- CSR build ----------------
__global__ void count_deg(const int* __restrict__ ei, int e) {
    int i = blockIdx.x * 256 + threadIdx.x;
    if (i >= e) return;
    atomicAdd(&g_deg[ei[e + i]], 1);
}

// One block: compute exclusive offsets of the 256-node chunks.
__global__ void chunk_offsets(int n, int nc) {
    __shared__ int sh[512];
    int t = threadIdx.x;
    int tot = 0;
    if (t < nc) {
        int base = t * 256;
        int lim = n - base; if (lim > 256) lim = 256;
        for (int j = 0; j < lim; j++) tot += g_deg[base + j];
    }
    sh[t] = tot;
    __syncthreads();
    for (int off = 1; off < 512; off <<= 1) {
        int v = (t >= off) ? sh[t - off] : 0;
        __syncthreads();
        sh[t] += v;
        __syncthreads();
    }
    g_bsum[t] = sh[t] - tot;   // exclusive
}

__global__ void scan_final(int n) {
    __shared__ int sh[256];
    int tid = threadIdx.x;
    int i = blockIdx.x * 256 + tid;
    int v = (i < n) ? g_deg[i] : 0;
    sh[tid] = v;
    __syncthreads();
    for (int off = 1; off < 256; off <<= 1) {
        int t = (tid >= off) ? sh[tid - off] : 0;
        __syncthreads();
        sh[tid] += t;
        __syncthreads();
    }
    int excl = sh[tid] - v + g_bsum[blockIdx.x];
    if (i < n) {
        g_rowstart[i] = excl;
        g_cursor[i]   = excl;
        g_dis[i] = rsqrtf((float)(v + 1));   // +1 self-loop
        if (i == n - 1) g_rowstart[n] = excl + v;
    }
}

__global__ void fill_csr(const int* __restrict__ ei, int e) {
    int i = blockIdx.x * 256 + threadIdx.x;
    if (i >= e) return;
    int s = ei[i];
    int d = ei[e + i];
    int pos = atomicAdd(&g_cursor[d], 1);
    g_csr[pos] = s;
}

// ---------------- layer 1: h~A = (x @ W1) * dis  -> fp16 ----------------
__global__ void gemm_in(const float4* __restrict__ x4, const float4* __restrict__ W1v, int n) {
    __shared__ float4 wt[512];   // W1 [128][16] row-major as float4
    int tid = threadIdx.x;
    for (int idx = tid; idx < 512; idx += 256) wt[idx] = W1v[idx];
    __syncthreads();

    int node = blockIdx.x * 256 + tid;
    if (node >= n) return;

    float acc[16];
#pragma unroll
    for (int j = 0; j < 16; j++) acc[j] = 0.f;

    const float4* xr = x4 + (size_t)node * 32;
    float4 xv[16];
#pragma unroll
    for (int half = 0; half < 2; half++) {
        int kb0 = half * 16;
#pragma unroll
        for (int i = 0; i < 16; i++) xv[i] = __ldg(&xr[kb0 + i]);
#pragma unroll
        for (int i = 0; i < 16; i++) {
            float4 v = xv[i];
            int kb = (kb0 + i) * 16;
#pragma unroll
            for (int j = 0; j < 4; j++) {
                float xs_ = (j == 0) ? v.x : (j == 1) ? v.y : (j == 2) ? v.z : v.w;
                float4 w0 = wt[kb + j * 4 + 0];
                float4 w1 = wt[kb + j * 4 + 1];
                float4 w2 = wt[kb + j * 4 + 2];
                float4 w3 = wt[kb + j * 4 + 3];
                acc[0]  += xs_ * w0.x; acc[1]  += xs_ * w0.y; acc[2]  += xs_ * w0.z; acc[3]  += xs_ * w0.w;
                acc[4]  += xs_ * w1.x; acc[5]  += xs_ * w1.y; acc[6]  += xs_ * w1.z; acc[7]  += xs_ * w1.w;
                acc[8]  += xs_ * w2.x; acc[9]  += xs_ * w2.y; acc[10] += xs_ * w2.z; acc[11] += xs_ * w2.w;
                acc[12] += xs_ * w3.x; acc[13] += xs_ * w3.y; acc[14] += xs_ * w3.z; acc[15] += xs_ * w3.w;
            }
        }
    }

    float d = g_dis[node];
#pragma unroll
    for (int q = 0; q < 4; q++)
        g_hA16[node * 4 + q] = make_uint2(pack2(acc[q*4+0]*d, acc[q*4+1]*d),
                                          pack2(acc[q*4+2]*d, acc[q*4+3]*d));
}

// ---------------- 16-wide fp16 gather: agg[i] = dis[i] * (sum h~[src] + h~[i]) ----------------
// One warp per node; lane q=lane&3 owns features 4q..4q+3 (one uint2 = 4 halves).
__global__ void gather16(int which, int n) {
    int w = (blockIdx.x * 256 + threadIdx.x) >> 5;
    if (w >= n) return;
    int lane = threadIdx.x & 31;
    int q = lane & 3, sub = lane >> 2;
    int start = g_rowstart[w], deg = g_rowstart[w + 1] - start;

    const uint2* __restrict__ h = (which == 0) ? g_hA16 : g_hB16;
    float4* __restrict__ agg    = (which == 0) ? g_aggA : g_aggB;

    float4 acc = make_float4(0.f, 0.f, 0.f, 0.f);
    for (int base = 0; base < deg; base += 32) {
        int p = base + lane;
        int idx = (p < deg) ? __ldg(&g_csr[start + p]) : 0;
        int s0 = __shfl_sync(0xffffffffu, idx, sub);
        int s1 = __shfl_sync(0xffffffffu, idx, sub + 8);
        int s2 = __shfl_sync(0xffffffffu, idx, sub + 16);
        int s3 = __shfl_sync(0xffffffffu, idx, sub + 24);
        uint2 z = make_uint2(0u, 0u);
        uint2 a = (base + sub)      < deg ? __ldg(&h[s0 * 4 + q]) : z;
        uint2 b = (base + sub + 8)  < deg ? __ldg(&h[s1 * 4 + q]) : z;
        uint2 c = (base + sub + 16) < deg ? __ldg(&h[s2 * 4 + q]) : z;
        uint2 d = (base + sub + 24) < deg ? __ldg(&h[s3 * 4 + q]) : z;
        float2 t;
        t = unpack2(a.x); acc.x += t.x; acc.y += t.y;
        t = unpack2(a.y); acc.z += t.x; acc.w += t.y;
        t = unpack2(b.x); acc.x += t.x; acc.y += t.y;
        t = unpack2(b.y); acc.z += t.x; acc.w += t.y;
        t = unpack2(c.x); acc.x += t.x; acc.y += t.y;
        t = unpack2(c.y); acc.z += t.x; acc.w += t.y;
        t = unpack2(d.x); acc.x += t.x; acc.y += t.y;
        t = unpack2(d.y); acc.z += t.x; acc.w += t.y;
    }
#pragma unroll
    for (int m = 4; m < 32; m <<= 1) {
        acc.x += __shfl_xor_sync(0xffffffffu, acc.x, m);
        acc.y += __shfl_xor_sync(0xffffffffu, acc.y, m);
        acc.z += __shfl_xor_sync(0xffffffffu, acc.z, m);
        acc.w += __shfl_xor_sync(0xffffffffu, acc.w, m);
    }
    if (sub == 0) {
        uint2 hv = __ldg(&h[w * 4 + q]);   // self-loop
        float2 t0 = unpack2(hv.x), t1 = unpack2(hv.y);
        float d = g_dis[w];
        agg[w * 4 + q] = make_float4((acc.x + t0.x) * d, (acc.y + t0.y) * d,
                                     (acc.z + t1.x) * d, (acc.w + t1.y) * d);
    }
}

// ---------------- layer 2: z = relu(aggA + b1); h~B = (z @ W2) * dis -> fp16 ----------------
__global__ void transform_mid(const float* __restrict__ bias, const float4* __restrict__ W, int n) {
    __shared__ float4 Ws[64];
    __shared__ float  bs[16];
    int tid = threadIdx.x;
    if (tid < 64) Ws[tid] = W[tid];
    if (tid < 16) bs[tid] = bias[tid];
    __syncthreads();
    int i = blockIdx.x * 256 + tid;
    if (i >= n) return;

    float z[16];
#pragma unroll
    for (int q = 0; q < 4; q++) {
        float4 v = g_aggA[i * 4 + q];
        z[q*4+0] = fmaxf(v.x + bs[q*4+0], 0.f);
        z[q*4+1] = fmaxf(v.y + bs[q*4+1], 0.f);
        z[q*4+2] = fmaxf(v.z + bs[q*4+2], 0.f);
        z[q*4+3] = fmaxf(v.w + bs[q*4+3], 0.f);
    }
    float4 o0 = make_float4(0.f,0.f,0.f,0.f), o1 = o0, o2 = o0, o3 = o0;
#pragma unroll
    for (int j = 0; j < 16; j++) {
        float zj = z[j];
        float4 w0 = Ws[j*4+0], w1 = Ws[j*4+1], w2 = Ws[j*4+2], w3 = Ws[j*4+3];
        o0.x += zj*w0.x; o0.y += zj*w0.y; o0.z += zj*w0.z; o0.w += zj*w0.w;
        o1.x += zj*w1.x; o1.y += zj*w1.y; o1.z += zj*w1.z; o1.w += zj*w1.w;
        o2.x += zj*w2.x; o2.y += zj*w2.y; o2.z += zj*w2.z; o2.w += zj*w2.w;
        o3.x += zj*w3.x; o3.y += zj*w3.y; o3.z += zj*w3.z; o3.w += zj*w3.w;
    }
    float d = g_dis[i];
    g_hB16[i*4+0] = make_uint2(pack2(o0.x*d, o0.y*d), pack2(o0.z*d, o0.w*d));
    g_hB16[i*4+1] = make_uint2(pack2(o1.x*d, o1.y*d), pack2(o1.z*d, o1.w*d));
    g_hB16[i*4+2] = make_uint2(pack2(o2.x*d, o2.y*d), pack2(o2.z*d, o2.w*d));
    g_hB16[i*4+3] = make_uint2(pack2(o3.x*d, o3.y*d), pack2(o3.z*d, o3.w*d));
}

// ---------------- layer 3: z = relu(aggB + b2); h~3 = (z @ W3) * dis ----------------
__global__ void transform_last(const float* __restrict__ bias, const float* __restrict__ W3, int n) {
    __shared__ float Ws[32];
    __shared__ float bs[16];
    int tid = threadIdx.x;
    if (tid < 32) Ws[tid] = W3[tid];
    if (tid < 16) bs[tid] = bias[tid];
    __syncthreads();
    int i = blockIdx.x * 256 + tid;
    if (i >= n) return;

    float z[16];
#pragma unroll
    for (int q = 0; q < 4; q++) {
        float4 v = g_aggB[i * 4 + q];
        z[q*4+0] = fmaxf(v.x + bs[q*4+0], 0.f);
        z[q*4+1] = fmaxf(v.y + bs[q*4+1], 0.f);
        z[q*4+2] = fmaxf(v.z + bs[q*4+2], 0.f);
        z[q*4+3] = fmaxf(v.w + bs[q*4+3], 0.f);
    }
    float o0 = 0.f, o1 = 0.f;
#pragma unroll
    for (int j = 0; j < 16; j++) {
        o0 += z[j] * Ws[j*2+0];
        o1 += z[j] * Ws[j*2+1];
    }
    float d = g_dis[i];
    g_h3[i] = make_float2(o0 * d, o1 * d);
}

// ---------------- 2-wide gather fused with log_softmax ----------------
__global__ void gather2_out(const float* __restrict__ b3, float* __restrict__ out, int n) {
    int w = (blockIdx.x * 256 + threadIdx.x) >> 5;
    if (w >= n) return;
    int lane = threadIdx.x & 31;
    int start = g_rowstart[w], end = g_rowstart[w + 1];

    float2 acc = make_float2(0.f, 0.f);
    for (int p = start + lane; p < end; p += 32) {
        int src = __ldg(&g_csr[p]);
        float2 v = __ldg(&g_h3[src]);
        acc.x += v.x; acc.y += v.y;
    }
#pragma unroll
    for (int m = 1; m < 32; m <<= 1) {
        acc.x += __shfl_xor_sync(0xffffffffu, acc.x, m);
        acc.y += __shfl_xor_sync(0xffffffffu, acc.y, m);
    }
    if (lane == 0) {
        float2 hv = g_h3[w];
        float d = g_dis[w];
        float a0 = (acc.x + hv.x) * d + b3[0];
        float a1 = (acc.y + hv.y) * d + b3[1];
        float m0 = fmaxf(a0, a1);
        float lse = m0 + logf(expf(a0 - m0) + expf(a1 - m0));
        out[w * 2 + 0] = a0 - lse;
        out[w * 2 + 1] = a1 - lse;
    }
}

// ---------------- launch ----------------
extern "C" void kernel_launch(void* const* d_in, const int* in_sizes, int n_in,
                              void* d_out, int out_size) {
    const float* x  = (const float*)d_in[0];
    const int*   ei = (const int*)d_in[1];
    const float* W1 = (const float*)d_in[2];
    const float* b1 = (const float*)d_in[3];
    const float* W2 = (const float*)d_in[4];
    const float* b2 = (const float*)d_in[5];
    const float* W3 = (const float*)d_in[6];
    const float* b3 = (const float*)d_in[7];
    float* out = (float*)d_out;

    int n = in_sizes[0] / 128;   // 100000
    int e = in_sizes[1] / 2;     // 3200000

    int nb  = (n + 255) / 256;       // 391
    int ebk = (e + 255) / 256;
    int wgb = (n * 32 + 255) / 256;  // warp-per-node grids

    void* degp = nullptr;
    cudaGetSymbolAddress(&degp, g_deg);
    cudaMemsetAsync(degp, 0, (size_t)n * sizeof(int));

    count_deg<<<ebk, 256>>>(ei, e);
    chunk_offsets<<<1, 512>>>(n, nb);
    scan_final<<<nb, 256>>>(n);
    fill_csr<<<ebk, 256>>>(ei, e);        // profiled slot (4th kernel)

    gemm_in<<<nb, 256>>>((const float4*)x, (const float4*)W1, n);
    gather16<<<wgb, 256>>>(0, n);

    transform_mid<<<nb, 256>>>(b1, (const float4*)W2, n);
    gather16<<<wgb, 256>>>(1, n);

    transform_last<<<nb, 256>>>(b2, W3, n);
    gather2_out<<<wgb, 256>>>(b3, out, n);
}

// round 8
// speedup vs baseline: 1.3447x; 1.3447x over previous
#include <cuda_runtime.h>
#include <cuda_fp16.h>

#define NN 100000
#define EE 3200000

// ---------------- persistent device scratch ----------------
__device__ int    g_deg[NN];
__device__ int    g_rank[EE];        // per-edge rank within destination
__device__ int    g_rowstart[NN + 1];
__device__ int    g_bsum[512];
__device__ int    g_csr[EE];
__device__ float  g_dis[NN];
__device__ uint2  g_hA16[NN * 4];    // h~ fp16: 16 halves = 32 B/node
__device__ uint2  g_hB16[NN * 4];
__device__ float4 g_aggA[NN * 4];    // aggregates fp32 (linear access)
__device__ float4 g_aggB[NN * 4];
__device__ float2 g_h3[NN];          // layer-3 h~ (2 f32/node)

// ---------------- fp16 pack/unpack ----------------
__device__ __forceinline__ unsigned pack2(float a, float b) {
    __half2 h = __floats2half2_rn(a, b);
    return *reinterpret_cast<unsigned*>(&h);
}
__device__ __forceinline__ float2 unpack2(unsigned u) {
    __half2 h = *reinterpret_cast<__half2*>(&u);
    return __half22float2(h);
}

// ---------------- CSR build ----------------
// count + rank in one pass: the atomic's return value IS the rank.
__global__ void count_rank(const int* __restrict__ ei, int e) {
    int i = blockIdx.x * 256 + threadIdx.x;
    if (i >= e) return;
    g_rank[i] = atomicAdd(&g_deg[ei[e + i]], 1);
}

__global__ void scan_block_totals(int n) {
    __shared__ int red[256];
    int tid = threadIdx.x;
    int i = blockIdx.x * 256 + tid;
    red[tid] = (i < n) ? g_deg[i] : 0;
    __syncthreads();
    for (int s = 128; s; s >>= 1) {
        if (tid < s) red[tid] += red[tid + s];
        __syncthreads();
    }
    if (tid == 0) g_bsum[blockIdx.x] = red[0];
}

__global__ void scan_bsums(int nb) {
    __shared__ int sh[512];
    int tid = threadIdx.x;
    int v = (tid < nb) ? g_bsum[tid] : 0;
    sh[tid] = v;
    __syncthreads();
    for (int off = 1; off < 512; off <<= 1) {
        int t = (tid >= off) ? sh[tid - off] : 0;
        __syncthreads();
        sh[tid] += t;
        __syncthreads();
    }
    g_bsum[tid] = sh[tid] - v;   // exclusive offsets
}

__global__ void scan_final(int n) {
    __shared__ int sh[256];
    int tid = threadIdx.x;
    int i = blockIdx.x * 256 + tid;
    int v = (i < n) ? g_deg[i] : 0;
    sh[tid] = v;
    __syncthreads();
    for (int off = 1; off < 256; off <<= 1) {
        int t = (tid >= off) ? sh[tid - off] : 0;
        __syncthreads();
        sh[tid] += t;
        __syncthreads();
    }
    int excl = sh[tid] - v + g_bsum[blockIdx.x];
    if (i < n) {
        g_rowstart[i] = excl;
        g_dis[i] = rsqrtf((float)(v + 1));   // +1 self-loop
        if (i == n - 1) g_rowstart[n] = excl + v;
    }
}

// No atomics: position = rowstart[dst] + precomputed rank. Fire-and-forget STG.
__global__ void fill_pos(const int* __restrict__ ei, int e) {
    int i = blockIdx.x * 256 + threadIdx.x;
    if (i >= e) return;
    int s = ei[i];
    int d = ei[e + i];
    g_csr[g_rowstart[d] + g_rank[i]] = s;
}

// ---------------- layer 1: h~A = (x @ W1) * dis  -> fp16 ----------------
__global__ void gemm_in(const float4* __restrict__ x4, const float4* __restrict__ W1v, int n) {
    __shared__ float4 wt[512];   // W1 [128][16] row-major as float4
    int tid = threadIdx.x;
    for (int idx = tid; idx < 512; idx += 256) wt[idx] = W1v[idx];
    __syncthreads();

    int node = blockIdx.x * 256 + tid;
    if (node >= n) return;

    float acc[16];
#pragma unroll
    for (int j = 0; j < 16; j++) acc[j] = 0.f;

    const float4* xr = x4 + (size_t)node * 32;
    float4 xv[16];
#pragma unroll
    for (int half = 0; half < 2; half++) {
        int kb0 = half * 16;
#pragma unroll
        for (int i = 0; i < 16; i++) xv[i] = __ldg(&xr[kb0 + i]);
#pragma unroll
        for (int i = 0; i < 16; i++) {
            float4 v = xv[i];
            int kb = (kb0 + i) * 16;
#pragma unroll
            for (int j = 0; j < 4; j++) {
                float xs_ = (j == 0) ? v.x : (j == 1) ? v.y : (j == 2) ? v.z : v.w;
                float4 w0 = wt[kb + j * 4 + 0];
                float4 w1 = wt[kb + j * 4 + 1];
                float4 w2 = wt[kb + j * 4 + 2];
                float4 w3 = wt[kb + j * 4 + 3];
                acc[0]  += xs_ * w0.x; acc[1]  += xs_ * w0.y; acc[2]  += xs_ * w0.z; acc[3]  += xs_ * w0.w;
                acc[4]  += xs_ * w1.x; acc[5]  += xs_ * w1.y; acc[6]  += xs_ * w1.z; acc[7]  += xs_ * w1.w;
                acc[8]  += xs_ * w2.x; acc[9]  += xs_ * w2.y; acc[10] += xs_ * w2.z; acc[11] += xs_ * w2.w;
                acc[12] += xs_ * w3.x; acc[13] += xs_ * w3.y; acc[14] += xs_ * w3.z; acc[15] += xs_ * w3.w;
            }
        }
    }

    float d = g_dis[node];
#pragma unroll
    for (int q = 0; q < 4; q++)
        g_hA16[node * 4 + q] = make_uint2(pack2(acc[q*4+0]*d, acc[q*4+1]*d),
                                          pack2(acc[q*4+2]*d, acc[q*4+3]*d));
}

// ---------------- 16-wide fp16 gather: agg[i] = dis[i] * (sum h~[src] + h~[i]) ----------------
__global__ void gather16(int which, int n) {
    int w = (blockIdx.x * 256 + threadIdx.x) >> 5;
    if (w >= n) return;
    int lane = threadIdx.x & 31;
    int q = lane & 3, sub = lane >> 2;
    int start = g_rowstart[w], deg = g_rowstart[w + 1] - start;

    const uint2* __restrict__ h = (which == 0) ? g_hA16 : g_hB16;
    float4* __restrict__ agg    = (which == 0) ? g_aggA : g_aggB;

    float4 acc = make_float4(0.f, 0.f, 0.f, 0.f);
    for (int base = 0; base < deg; base += 32) {
        int p = base + lane;
        int idx = (p < deg) ? __ldg(&g_csr[start + p]) : 0;
        int s0 = __shfl_sync(0xffffffffu, idx, sub);
        int s1 = __shfl_sync(0xffffffffu, idx, sub + 8);
        int s2 = __shfl_sync(0xffffffffu, idx, sub + 16);
        int s3 = __shfl_sync(0xffffffffu, idx, sub + 24);
        uint2 z = make_uint2(0u, 0u);
        uint2 a = (base + sub)      < deg ? __ldg(&h[s0 * 4 + q]) : z;
        uint2 b = (base + sub + 8)  < deg ? __ldg(&h[s1 * 4 + q]) : z;
        uint2 c = (base + sub + 16) < deg ? __ldg(&h[s2 * 4 + q]) : z;
        uint2 d = (base + sub + 24) < deg ? __ldg(&h[s3 * 4 + q]) : z;
        float2 t;
        t = unpack2(a.x); acc.x += t.x; acc.y += t.y;
        t = unpack2(a.y); acc.z += t.x; acc.w += t.y;
        t = unpack2(b.x); acc.x += t.x; acc.y += t.y;
        t = unpack2(b.y); acc.z += t.x; acc.w += t.y;
        t = unpack2(c.x); acc.x += t.x; acc.y += t.y;
        t = unpack2(c.y); acc.z += t.x; acc.w += t.y;
        t = unpack2(d.x); acc.x += t.x; acc.y += t.y;
        t = unpack2(d.y); acc.z += t.x; acc.w += t.y;
    }
#pragma unroll
    for (int m = 4; m < 32; m <<= 1) {
        acc.x += __shfl_xor_sync(0xffffffffu, acc.x, m);
        acc.y += __shfl_xor_sync(0xffffffffu, acc.y, m);
        acc.z += __shfl_xor_sync(0xffffffffu, acc.z, m);
        acc.w += __shfl_xor_sync(0xffffffffu, acc.w, m);
    }
    if (sub == 0) {
        uint2 hv = __ldg(&h[w * 4 + q]);   // self-loop
        float2 t0 = unpack2(hv.x), t1 = unpack2(hv.y);
        float d = g_dis[w];
        agg[w * 4 + q] = make_float4((acc.x + t0.x) * d, (acc.y + t0.y) * d,
                                     (acc.z + t1.x) * d, (acc.w + t1.y) * d);
    }
}

// ---------------- layer 2: z = relu(aggA + b1); h~B = (z @ W2) * dis -> fp16 ----------------
__global__ void transform_mid(const float* __restrict__ bias, const float4* __restrict__ W, int n) {
    __shared__ float4 Ws[64];
    __shared__ float  bs[16];
    int tid = threadIdx.x;
    if (tid < 64) Ws[tid] = W[tid];
    if (tid < 16) bs[tid] = bias[tid];
    __syncthreads();
    int i = blockIdx.x * 256 + tid;
    if (i >= n) return;

    float z[16];
#pragma unroll
    for (int q = 0; q < 4; q++) {
        float4 v = g_aggA[i * 4 + q];
        z[q*4+0] = fmaxf(v.x + bs[q*4+0], 0.f);
        z[q*4+1] = fmaxf(v.y + bs[q*4+1], 0.f);
        z[q*4+2] = fmaxf(v.z + bs[q*4+2], 0.f);
        z[q*4+3] = fmaxf(v.w + bs[q*4+3], 0.f);
    }
    float4 o0 = make_float4(0.f,0.f,0.f,0.f), o1 = o0, o2 = o0, o3 = o0;
#pragma unroll
    for (int j = 0; j < 16; j++) {
        float zj = z[j];
        float4 w0 = Ws[j*4+0], w1 = Ws[j*4+1], w2 = Ws[j*4+2], w3 = Ws[j*4+3];
        o0.x += zj*w0.x; o0.y += zj*w0.y; o0.z += zj*w0.z; o0.w += zj*w0.w;
        o1.x += zj*w1.x; o1.y += zj*w1.y; o1.z += zj*w1.z; o1.w += zj*w1.w;
        o2.x += zj*w2.x; o2.y += zj*w2.y; o2.z += zj*w2.z; o2.w += zj*w2.w;
        o3.x += zj*w3.x; o3.y += zj*w3.y; o3.z += zj*w3.z; o3.w += zj*w3.w;
    }
    float d = g_dis[i];
    g_hB16[i*4+0] = make_uint2(pack2(o0.x*d, o0.y*d), pack2(o0.z*d, o0.w*d));
    g_hB16[i*4+1] = make_uint2(pack2(o1.x*d, o1.y*d), pack2(o1.z*d, o1.w*d));
    g_hB16[i*4+2] = make_uint2(pack2(o2.x*d, o2.y*d), pack2(o2.z*d, o2.w*d));
    g_hB16[i*4+3] = make_uint2(pack2(o3.x*d, o3.y*d), pack2(o3.z*d, o3.w*d));
}

// ---------------- layer 3: z = relu(aggB + b2); h~3 = (z @ W3) * dis ----------------
__global__ void transform_last(const float* __restrict__ bias, const float* __restrict__ W3, int n) {
    __shared__ float Ws[32];
    __shared__ float bs[16];
    int tid = threadIdx.x;
    if (tid < 32) Ws[tid] = W3[tid];
    if (tid < 16) bs[tid] = bias[tid];
    __syncthreads();
    int i = blockIdx.x * 256 + tid;
    if (i >= n) return;

    float z[16];
#pragma unroll
    for (int q = 0; q < 4; q++) {
        float4 v = g_aggB[i * 4 + q];
        z[q*4+0] = fmaxf(v.x + bs[q*4+0], 0.f);
        z[q*4+1] = fmaxf(v.y + bs[q*4+1], 0.f);
        z[q*4+2] = fmaxf(v.z + bs[q*4+2], 0.f);
        z[q*4+3] = fmaxf(v.w + bs[q*4+3], 0.f);
    }
    float o0 = 0.f, o1 = 0.f;
#pragma unroll
    for (int j = 0; j < 16; j++) {
        o0 += z[j] * Ws[j*2+0];
        o1 += z[j] * Ws[j*2+1];
    }
    float d = g_dis[i];
    g_h3[i] = make_float2(o0 * d, o1 * d);
}

// ---------------- 2-wide gather fused with log_softmax ----------------
__global__ void gather2_out(const float* __restrict__ b3, float* __restrict__ out, int n) {
    int w = (blockIdx.x * 256 + threadIdx.x) >> 5;
    if (w >= n) return;
    int lane = threadIdx.x & 31;
    int start = g_rowstart[w], end = g_rowstart[w + 1];

    float2 acc = make_float2(0.f, 0.f);
    for (int p = start + lane; p < end; p += 32) {
        int src = __ldg(&g_csr[p]);
        float2 v = __ldg(&g_h3[src]);
        acc.x += v.x; acc.y += v.y;
    }
#pragma unroll
    for (int m = 1; m < 32; m <<= 1) {
        acc.x += __shfl_xor_sync(0xffffffffu, acc.x, m);
        acc.y += __shfl_xor_sync(0xffffffffu, acc.y, m);
    }
    if (lane == 0) {
        float2 hv = g_h3[w];
        float d = g_dis[w];
        float a0 = (acc.x + hv.x) * d + b3[0];
        float a1 = (acc.y + hv.y) * d + b3[1];
        float m0 = fmaxf(a0, a1);
        float lse = m0 + logf(expf(a0 - m0) + expf(a1 - m0));
        out[w * 2 + 0] = a0 - lse;
        out[w * 2 + 1] = a1 - lse;
    }
}

// ---------------- launch ----------------
extern "C" void kernel_launch(void* const* d_in, const int* in_sizes, int n_in,
                              void* d_out, int out_size) {
    const float* x  = (const float*)d_in[0];
    const int*   ei = (const int*)d_in[1];
    const float* W1 = (const float*)d_in[2];
    const float* b1 = (const float*)d_in[3];
    const float* W2 = (const float*)d_in[4];
    const float* b2 = (const float*)d_in[5];
    const float* W3 = (const float*)d_in[6];
    const float* b3 = (const float*)d_in[7];
    float* out = (float*)d_out;

    int n = in_sizes[0] / 128;   // 100000
    int e = in_sizes[1] / 2;     // 3200000

    int nb  = (n + 255) / 256;       // 391
    int ebk = (e + 255) / 256;
    int wgb = (n * 32 + 255) / 256;  // warp-per-node grids

    void* degp = nullptr;
    cudaGetSymbolAddress(&degp, g_deg);
    cudaMemsetAsync(degp, 0, (size_t)n * sizeof(int));

    count_rank<<<ebk, 256>>>(ei, e);
    scan_block_totals<<<nb, 256>>>(n);
    scan_bsums<<<1, 512>>>(nb);
    scan_final<<<nb, 256>>>(n);
    fill_pos<<<ebk, 256>>>(ei, e);

    gemm_in<<<nb, 256>>>((const float4*)x, (const float4*)W1, n);
    gather16<<<wgb, 256>>>(0, n);

    transform_mid<<<nb, 256>>>(b1, (const float4*)W2, n);
    gather16<<<wgb, 256>>>(1, n);

    transform_last<<<nb, 256>>>(b2, W3, n);
    gather2_out<<<wgb, 256>>>(b3, out, n);
}